// round 10
// baseline (speedup 1.0000x reference)
#include <cuda_runtime.h>
#include <cuda_fp16.h>
#include <cstdint>

// TM-CFAR: out = rd_map / trimmed_mean(sorted 126 reference cells, ranks [31,94))
// Window 9x15, guard 3x3, zero padding.
//
// Round-10: round-9 structure (warp per 4 pixels, byte-packed 128-bin histogram)
// with register-pressure fixes to recover occupancy:
//  - __launch_bounds__(256,7): 7 blocks/SM (regs <= 36)
//  - center pixel re-loaded at the store (not held across the loop)
//  - exact-path predicate precomputed as an 8-bit quad mask

#define TILE_WP   80      // packed tile stride in u32 (80 % 32 == 16: bank spread)
#define TILE_COLS 46
#define TILE_ROWS 16
#define KBIAS     1024
#define KSCALE    30720.0f
#define SENT2     0x7BFF7BFFu   // max-finite fp16: never below any threshold, hmul-safe

static __device__ __forceinline__ unsigned h2u(__half2 h) { return *reinterpret_cast<unsigned*>(&h); }
static __device__ __forceinline__ __half2  u2h(unsigned u) { return *reinterpret_cast<__half2*>(&u); }

// STARTBIT < STOPBIT => zero bisection steps, epilogue only, MIDOFF = 1<<(STOPBIT-1)
template <int STARTBIT, int STOPBIT>
static __device__ __forceinline__ void bisect_pair(
    unsigned pk0, unsigned pk1, unsigned pk2, unsigned pk3,
    unsigned A2, unsigned B2,
    float& scP, float& scQ)
{
    const __half2 magic = u2h(0x64006400u);   // (1024.0, 1024.0)

    #pragma unroll
    for (int bit = STARTBIT; bit >= STOPBIT; --bit) {
        const unsigned step2 = (1u << bit) * 0x10001u;
        const __half2 mA = u2h(A2 + step2);
        const __half2 mB = u2h(B2 + step2);

        __half2 sA = __hadd2(__hadd2(__hlt2(u2h(pk0), mA), __hlt2(u2h(pk1), mA)),
                             __hadd2(__hlt2(u2h(pk2), mA), __hlt2(u2h(pk3), mA)));
        __half2 sB = __hadd2(__hadd2(__hlt2(u2h(pk0), mB), __hlt2(u2h(pk1), mB)),
                             __hadd2(__hlt2(u2h(pk2), mB), __hlt2(u2h(pk3), mB)));
        const unsigned Ar = h2u(__hadd2(sA, magic));   // bytes (cAP, 0x64, cAQ, 0x64)
        const unsigned Br = h2u(__hadd2(sB, magic));
        unsigned cc = __byte_perm(Ar, Br, 0x6420);     // (cAP, cAQ, cBP, cBQ)
        cc = __reduce_add_sync(0xffffffffu, cc);

        // byte-wise accept flags: bytes 0,1 vs 30 ; bytes 2,3 vs 94
        const unsigned f = ((0xDEDE9E9Eu - cc) >> 7) & 0x01010101u;
        A2 += __byte_perm(f, 0, 0x4140) << bit;   // (fAP | fAQ<<16) << bit
        B2 += __byte_perm(f, 0, 0x4342) << bit;
    }

    const int MIDOFF = (STOPBIT > 0) ? (1 << (STOPBIT - 1)) : 0;

    // ---- epilogue: exact counts below brackets + masked range sums ----
    const __half2 hA = u2h(A2), hB = u2h(B2);
    const __half2 lA0 = __hlt2(u2h(pk0), hA), lA1 = __hlt2(u2h(pk1), hA);
    const __half2 lA2v = __hlt2(u2h(pk2), hA), lA3 = __hlt2(u2h(pk3), hA);
    const __half2 lB0 = __hlt2(u2h(pk0), hB), lB1 = __hlt2(u2h(pk1), hB);
    const __half2 lB2v = __hlt2(u2h(pk2), hB), lB3 = __hlt2(u2h(pk3), hB);

    const unsigned in0 = h2u(lB0) & ~h2u(lA0);
    const unsigned in1 = h2u(lB1) & ~h2u(lA1);
    const unsigned in2 = h2u(lB2v) & ~h2u(lA2v);
    const unsigned in3 = h2u(lB3) & ~h2u(lA3);

    const unsigned km0 = h2u(__hmul2(u2h(pk0), u2h(in0)));
    const unsigned km1 = h2u(__hmul2(u2h(pk1), u2h(in1)));
    const unsigned km2 = h2u(__hmul2(u2h(pk2), u2h(in2)));
    const unsigned km3 = h2u(__hmul2(u2h(pk3), u2h(in3)));

    // halfword-pair pack + SIMD add (lanes <= 2*31743, no carry)
    const unsigned lo01 = __byte_perm(km0, km1, 0x5410);
    const unsigned lo23 = __byte_perm(km2, km3, 0x5410);
    const unsigned hi01 = __byte_perm(km0, km1, 0x7632);
    const unsigned hi23 = __byte_perm(km2, km3, 0x7632);
    const unsigned vlo = __vadd2(lo01, lo23);
    const unsigned vhi = __vadd2(hi01, hi23);
    unsigned sP = (vlo & 0xFFFFu) + (vlo >> 16);
    unsigned sQ = (vhi & 0xFFFFu) + (vhi >> 16);

    const __half2 cA2 = __hadd2(__hadd2(lA0, lA1), __hadd2(lA2v, lA3));
    const __half2 cB2 = __hadd2(__hadd2(lB0, lB1), __hadd2(lB2v, lB3));
    unsigned ccf = __byte_perm(h2u(__hadd2(cA2, magic)), h2u(__hadd2(cB2, magic)), 0x6420);

    ccf = __reduce_add_sync(0xffffffffu, ccf);
    sP  = __reduce_add_sync(0xffffffffu, sP);
    sQ  = __reduce_add_sync(0xffffffffu, sQ);

    const int cAP = (int)(ccf & 255u);
    const int cAQ = (int)((ccf >> 8) & 255u);
    const int cBP = (int)((ccf >> 16) & 255u);
    const int cBQ = (int)(ccf >> 24);

    const int TAP = (int)(A2 & 0xFFFFu) + MIDOFF, TAQ = (int)(A2 >> 16) + MIDOFF;
    const int TBP = (int)(B2 & 0xFFFFu) + MIDOFF, TBQ = (int)(B2 >> 16) + MIDOFF;

    const int keptP = (int)sP - KBIAS * (cBP - cAP)
                    + (94 - cBP) * (TBP - KBIAS) - (31 - cAP) * (TAP - KBIAS);
    const int keptQ = (int)sQ - KBIAS * (cBQ - cAQ)
                    + (94 - cBQ) * (TBQ - KBIAS) - (31 - cAQ) * (TAQ - KBIAS);

    scP = __fdividef(63.0f * KSCALE, (float)keptP);
    scQ = __fdividef(63.0f * KSCALE, (float)keptQ);
}

__global__ __launch_bounds__(256, 7)
void tmcfar_kernel(const float* __restrict__ in, float* __restrict__ out,
                   int H, int W)
{
    __shared__ unsigned keypack[TILE_ROWS * TILE_WP];        // 5120 B
    __shared__ int      offs[128];                           // u32-element offsets
    __shared__ __align__(16) unsigned hist[8][128];          // byte p = pixel p count

    const int tid  = threadIdx.x;
    const int lane = tid & 31;
    const int wrp  = tid >> 5;
    const int bz   = blockIdx.z;
    const int py0  = blockIdx.y * 8;
    const int px0  = blockIdx.x * 32;

    // compacted (dy,dx) offsets of the 126 reference cells (u32-element units)
    if (tid < 135) {
        int r = tid / 15, c = tid - r * 15;
        bool guard = (r >= 3 && r <= 5 && c >= 6 && c <= 8);
        if (!guard) {
            int rowsBefore = min(max(r - 3, 0), 3);
            int sameRow    = (r >= 3 && r <= 5) ? min(max(c - 6, 0), 3) : 0;
            int gb = 3 * rowsBefore + sameRow;
            offs[tid - gb] = (r - 4) * TILE_WP + (c - 7);
        }
    }

    // load + quantize directly into packed tile: entry c = key[c] | key[c+1]<<16
    const int gy0 = py0 - 4, gx0 = px0 - 7;
    const float* inb = in + (size_t)bz * H * W;
    for (int idx = tid; idx < TILE_ROWS * 64; idx += 256) {
        int r = idx >> 6, c = idx & 63;
        if (c < TILE_COLS - 1) {
            int gy = gy0 + r, gx = gx0 + c;
            bool okr = (gy >= 0 && gy < H);
            float v0 = (okr && gx >= 0     && gx < W)     ? inb[gy * W + gx]     : 0.0f;
            float v1 = (okr && gx + 1 >= 0 && gx + 1 < W) ? inb[gy * W + gx + 1] : 0.0f;
            unsigned k0 = min((unsigned)(v0 * KSCALE), 30719u) + (unsigned)KBIAS;
            unsigned k1 = min((unsigned)(v1 * KSCALE), 30719u) + (unsigned)KBIAS;
            keypack[r * TILE_WP + c] = k0 | (k1 << 16);
        }
    }
    __syncthreads();

    const int py = py0 + wrp;

    // 8-bit mask: quad i needs the exact path (window touches zero padding)
    unsigned exmask = 0;
    {
        const bool exY = (py < 4) | (py >= H - 4);
        #pragma unroll
        for (int i = 0; i < 8; ++i) {
            const int pxP = px0 + 4 * i;
            if (exY | (pxP < 7) | (pxP + 3 >= W - 7)) exmask |= (1u << i);
        }
    }

    const int o0 = offs[lane];
    const int o1 = offs[lane + 32];
    const int o2 = offs[lane + 64];
    const int o3 = (lane < 30) ? offs[lane + 96] : 0;
    const bool has3 = (lane < 30);

    const unsigned* basep = &keypack[(wrp + 4) * TILE_WP + 7];
    unsigned* hst = &hist[wrp][0];
    float myscale = 0.0f;

    #pragma unroll 1
    for (int i = 0; i < 8; ++i) {
        const unsigned* p = basep + 4 * i;
        // pair (P,Q) words and pair (R,S) words (R = P+2)
        const unsigned a0 = p[o0],     b0 = p[o0 + 2];
        const unsigned a1 = p[o1],     b1 = p[o1 + 2];
        const unsigned a2 = p[o2],     b2 = p[o2 + 2];
        const unsigned a3 = has3 ? p[o3]     : SENT2;
        const unsigned b3 = has3 ? p[o3 + 2] : SENT2;

        // ---- byte-packed 128-bin histogram (bin = key>>8; SENT->bin 123, harmless) ----
        *reinterpret_cast<uint4*>(&hst[lane * 4]) = make_uint4(0u, 0u, 0u, 0u);
        __syncwarp();
        atomicAdd(&hst[(a0 >> 8) & 0xFFu], 1u);         atomicAdd(&hst[a0 >> 24], 0x100u);
        atomicAdd(&hst[(a1 >> 8) & 0xFFu], 1u);         atomicAdd(&hst[a1 >> 24], 0x100u);
        atomicAdd(&hst[(a2 >> 8) & 0xFFu], 1u);         atomicAdd(&hst[a2 >> 24], 0x100u);
        atomicAdd(&hst[(a3 >> 8) & 0xFFu], 1u);         atomicAdd(&hst[a3 >> 24], 0x100u);
        atomicAdd(&hst[(b0 >> 8) & 0xFFu], 0x10000u);   atomicAdd(&hst[b0 >> 24], 0x1000000u);
        atomicAdd(&hst[(b1 >> 8) & 0xFFu], 0x10000u);   atomicAdd(&hst[b1 >> 24], 0x1000000u);
        atomicAdd(&hst[(b2 >> 8) & 0xFFu], 0x10000u);   atomicAdd(&hst[b2 >> 24], 0x1000000u);
        atomicAdd(&hst[(b3 >> 8) & 0xFFu], 0x10000u);   atomicAdd(&hst[b3 >> 24], 0x1000000u);
        __syncwarp();

        // ---- lane-serial byte-SIMD prefix + ONE packed warp scan (bytes <= 128) ----
        const uint4 cw = *reinterpret_cast<const uint4*>(&hst[lane * 4]);
        unsigned q0 = cw.x;
        unsigned q1 = q0 + cw.y;
        unsigned q2 = q1 + cw.z;
        unsigned q3 = q2 + cw.w;
        unsigned incl = q3;
        #pragma unroll
        for (int d = 1; d < 32; d <<= 1) {
            unsigned t = __shfl_up_sync(0xffffffffu, incl, d);
            if (lane >= d) incl += t;
        }
        const unsigned excl = incl - q3;
        q0 += excl; q1 += excl; q2 += excl; q3 += excl;

        // ---- byte-SIMD bucket search for all 4 pixels, TWO REDUX total ----
        const unsigned g30 = (((0x9E9E9E9Eu - q0) >> 7) & 0x01010101u)
                           + (((0x9E9E9E9Eu - q1) >> 7) & 0x01010101u)
                           + (((0x9E9E9E9Eu - q2) >> 7) & 0x01010101u)
                           + (((0x9E9E9E9Eu - q3) >> 7) & 0x01010101u);
        const unsigned g94 = (((0xDEDEDEDEu - q0) >> 7) & 0x01010101u)
                           + (((0xDEDEDEDEu - q1) >> 7) & 0x01010101u)
                           + (((0xDEDEDEDEu - q2) >> 7) & 0x01010101u)
                           + (((0xDEDEDEDEu - q3) >> 7) & 0x01010101u);
        const unsigned w30 = __reduce_add_sync(0xffffffffu, g30);  // bytes (bAP,bAQ,bAR,bAS)
        const unsigned w94 = __reduce_add_sync(0xffffffffu, g94);  // bytes (bBP,bBQ,bBR,bBS)

        // bucket base = bin<<8: bytes to halfword-high positions per pair
        const unsigned A2pq = __byte_perm(w30, 0, 0x1404);   // (0,bAP,0,bAQ)
        const unsigned B2pq = __byte_perm(w94, 0, 0x1404);
        const unsigned A2rs = __byte_perm(w30, 0, 0x3424);   // (0,bAR,0,bAS)
        const unsigned B2rs = __byte_perm(w94, 0, 0x3424);

        float s0, s1, s2, s3;
        if ((exmask >> i) & 1u) {
            // window touches zero padding: 8 exact bisection steps inside bucket
            bisect_pair<7, 0>(a0, a1, a2, a3, A2pq, B2pq, s0, s1);
            bisect_pair<7, 0>(b0, b1, b2, b3, A2rs, B2rs, s2, s3);
        } else {
            // clean: 256-wide bucket direct, midpoint +-128 substitution
            bisect_pair<7, 8>(a0, a1, a2, a3, A2pq, B2pq, s0, s1);
            bisect_pair<7, 8>(b0, b1, b2, b3, A2rs, B2rs, s2, s3);
        }
        if (lane == 4 * i)     myscale = s0;
        if (lane == 4 * i + 1) myscale = s1;
        if (lane == 4 * i + 2) myscale = s2;
        if (lane == 4 * i + 3) myscale = s3;
    }

    // center pixel re-loaded here (coalesced; DRAM idle) instead of held in a reg
    const size_t oidx = (size_t)bz * H * W + py * W + px0 + lane;
    out[oidx] = inb[py * W + px0 + lane] * myscale;
}

extern "C" void kernel_launch(void* const* d_in, const int* in_sizes, int n_in,
                              void* d_out, int out_size)
{
    const float* in = (const float*)d_in[0];
    float* out = (float*)d_out;
    const int H = 512, W = 512;
    const int B = in_sizes[0] / (H * W);

    dim3 grid(W / 32, H / 8, B);
    dim3 block(256);
    tmcfar_kernel<<<grid, block>>>(in, out, H, W);
}

// round 11
// speedup vs baseline: 1.0253x; 1.0253x over previous
#include <cuda_runtime.h>
#include <cuda_fp16.h>
#include <cstdint>

// TM-CFAR: out = rd_map / trimmed_mean(sorted 126 reference cells, ranks [31,94))
// Window 9x15, guard 3x3, zero padding.
//
// Round-11 = round-9 (warp per 4 pixels, byte-packed 128-bin histogram,
// __launch_bounds__(256,6)) + qword key tile:
//  - qword[c] = (k[c],k[c+1],k[c+2],k[c+3]) as 4xu16 -> ONE LDS.64 per
//    reference cell serves all 4 pixels (was 2x LDS.32 + 2 addr calcs)

#define TILE_WQ   50      // qword tile stride (u64 units)
#define PAIR_W    48      // transient pair-tile stride (u32 units)
#define TILE_COLS 46
#define TILE_ROWS 16
#define KBIAS     1024
#define KSCALE    30720.0f
#define SENT2     0x7BFF7BFFu   // max-finite fp16: never below any threshold, hmul-safe

static __device__ __forceinline__ unsigned h2u(__half2 h) { return *reinterpret_cast<unsigned*>(&h); }
static __device__ __forceinline__ __half2  u2h(unsigned u) { return *reinterpret_cast<__half2*>(&u); }

// STARTBIT < STOPBIT => zero bisection steps, epilogue only, MIDOFF = 1<<(STOPBIT-1)
template <int STARTBIT, int STOPBIT>
static __device__ __forceinline__ void bisect_pair(
    unsigned pk0, unsigned pk1, unsigned pk2, unsigned pk3,
    unsigned A2, unsigned B2,
    float& scP, float& scQ)
{
    const __half2 magic = u2h(0x64006400u);   // (1024.0, 1024.0)

    #pragma unroll
    for (int bit = STARTBIT; bit >= STOPBIT; --bit) {
        const unsigned step2 = (1u << bit) * 0x10001u;
        const __half2 mA = u2h(A2 + step2);
        const __half2 mB = u2h(B2 + step2);

        __half2 sA = __hadd2(__hadd2(__hlt2(u2h(pk0), mA), __hlt2(u2h(pk1), mA)),
                             __hadd2(__hlt2(u2h(pk2), mA), __hlt2(u2h(pk3), mA)));
        __half2 sB = __hadd2(__hadd2(__hlt2(u2h(pk0), mB), __hlt2(u2h(pk1), mB)),
                             __hadd2(__hlt2(u2h(pk2), mB), __hlt2(u2h(pk3), mB)));
        const unsigned Ar = h2u(__hadd2(sA, magic));   // bytes (cAP, 0x64, cAQ, 0x64)
        const unsigned Br = h2u(__hadd2(sB, magic));
        unsigned cc = __byte_perm(Ar, Br, 0x6420);     // (cAP, cAQ, cBP, cBQ)
        cc = __reduce_add_sync(0xffffffffu, cc);

        // byte-wise accept flags: bytes 0,1 vs 30 ; bytes 2,3 vs 94
        const unsigned f = ((0xDEDE9E9Eu - cc) >> 7) & 0x01010101u;
        A2 += __byte_perm(f, 0, 0x4140) << bit;   // (fAP | fAQ<<16) << bit
        B2 += __byte_perm(f, 0, 0x4342) << bit;
    }

    const int MIDOFF = (STOPBIT > 0) ? (1 << (STOPBIT - 1)) : 0;

    // ---- epilogue: exact counts below brackets + masked range sums ----
    const __half2 hA = u2h(A2), hB = u2h(B2);
    const __half2 lA0 = __hlt2(u2h(pk0), hA), lA1 = __hlt2(u2h(pk1), hA);
    const __half2 lA2v = __hlt2(u2h(pk2), hA), lA3 = __hlt2(u2h(pk3), hA);
    const __half2 lB0 = __hlt2(u2h(pk0), hB), lB1 = __hlt2(u2h(pk1), hB);
    const __half2 lB2v = __hlt2(u2h(pk2), hB), lB3 = __hlt2(u2h(pk3), hB);

    const unsigned in0 = h2u(lB0) & ~h2u(lA0);
    const unsigned in1 = h2u(lB1) & ~h2u(lA1);
    const unsigned in2 = h2u(lB2v) & ~h2u(lA2v);
    const unsigned in3 = h2u(lB3) & ~h2u(lA3);

    const unsigned km0 = h2u(__hmul2(u2h(pk0), u2h(in0)));
    const unsigned km1 = h2u(__hmul2(u2h(pk1), u2h(in1)));
    const unsigned km2 = h2u(__hmul2(u2h(pk2), u2h(in2)));
    const unsigned km3 = h2u(__hmul2(u2h(pk3), u2h(in3)));

    // halfword-pair pack + SIMD add (lanes <= 2*31743, no carry)
    const unsigned lo01 = __byte_perm(km0, km1, 0x5410);
    const unsigned lo23 = __byte_perm(km2, km3, 0x5410);
    const unsigned hi01 = __byte_perm(km0, km1, 0x7632);
    const unsigned hi23 = __byte_perm(km2, km3, 0x7632);
    const unsigned vlo = __vadd2(lo01, lo23);
    const unsigned vhi = __vadd2(hi01, hi23);
    unsigned sP = (vlo & 0xFFFFu) + (vlo >> 16);
    unsigned sQ = (vhi & 0xFFFFu) + (vhi >> 16);

    const __half2 cA2 = __hadd2(__hadd2(lA0, lA1), __hadd2(lA2v, lA3));
    const __half2 cB2 = __hadd2(__hadd2(lB0, lB1), __hadd2(lB2v, lB3));
    unsigned ccf = __byte_perm(h2u(__hadd2(cA2, magic)), h2u(__hadd2(cB2, magic)), 0x6420);

    ccf = __reduce_add_sync(0xffffffffu, ccf);
    sP  = __reduce_add_sync(0xffffffffu, sP);
    sQ  = __reduce_add_sync(0xffffffffu, sQ);

    const int cAP = (int)(ccf & 255u);
    const int cAQ = (int)((ccf >> 8) & 255u);
    const int cBP = (int)((ccf >> 16) & 255u);
    const int cBQ = (int)(ccf >> 24);

    const int TAP = (int)(A2 & 0xFFFFu) + MIDOFF, TAQ = (int)(A2 >> 16) + MIDOFF;
    const int TBP = (int)(B2 & 0xFFFFu) + MIDOFF, TBQ = (int)(B2 >> 16) + MIDOFF;

    const int keptP = (int)sP - KBIAS * (cBP - cAP)
                    + (94 - cBP) * (TBP - KBIAS) - (31 - cAP) * (TAP - KBIAS);
    const int keptQ = (int)sQ - KBIAS * (cBQ - cAQ)
                    + (94 - cBQ) * (TBQ - KBIAS) - (31 - cAQ) * (TAQ - KBIAS);

    scP = __fdividef(63.0f * KSCALE, (float)keptP);
    scQ = __fdividef(63.0f * KSCALE, (float)keptQ);
}

__global__ __launch_bounds__(256, 6)
void tmcfar_kernel(const float* __restrict__ in, float* __restrict__ out,
                   int H, int W)
{
    __shared__ unsigned pairs[TILE_ROWS * PAIR_W];            // 3072 B (build only)
    __shared__ unsigned long long qtile[TILE_ROWS * TILE_WQ]; // 6400 B
    __shared__ int      offs[128];                            // qword-unit offsets
    __shared__ __align__(16) unsigned hist[8][128];           // byte p = pixel p count

    const int tid  = threadIdx.x;
    const int lane = tid & 31;
    const int wrp  = tid >> 5;
    const int bz   = blockIdx.z;
    const int py0  = blockIdx.y * 8;
    const int px0  = blockIdx.x * 32;

    // compacted (dy,dx) offsets of the 126 reference cells (qword units)
    if (tid < 135) {
        int r = tid / 15, c = tid - r * 15;
        bool guard = (r >= 3 && r <= 5 && c >= 6 && c <= 8);
        if (!guard) {
            int rowsBefore = min(max(r - 3, 0), 3);
            int sameRow    = (r >= 3 && r <= 5) ? min(max(c - 6, 0), 3) : 0;
            int gb = 3 * rowsBefore + sameRow;
            offs[tid - gb] = (r - 4) * TILE_WQ + (c - 7);
        }
    }

    // ---- phase 1: pair tile, entry c = key[c] | key[c+1]<<16 (c in 0..44) ----
    const int gy0 = py0 - 4, gx0 = px0 - 7;
    const float* inb = in + (size_t)bz * H * W;
    for (int idx = tid; idx < TILE_ROWS * PAIR_W; idx += 256) {
        int r = idx / PAIR_W, c = idx - r * PAIR_W;
        if (c < TILE_COLS - 1) {
            int gy = gy0 + r, gx = gx0 + c;
            bool okr = (gy >= 0 && gy < H);
            float v0 = (okr && gx >= 0     && gx < W)     ? inb[gy * W + gx]     : 0.0f;
            float v1 = (okr && gx + 1 >= 0 && gx + 1 < W) ? inb[gy * W + gx + 1] : 0.0f;
            unsigned k0 = min((unsigned)(v0 * KSCALE), 30719u) + (unsigned)KBIAS;
            unsigned k1 = min((unsigned)(v1 * KSCALE), 30719u) + (unsigned)KBIAS;
            pairs[r * PAIR_W + c] = k0 | (k1 << 16);
        }
    }
    __syncthreads();

    // ---- phase 2: qword tile, entry c = (pairs[c], pairs[c+2]) = k[c..c+3] ----
    for (int idx = tid; idx < TILE_ROWS * 44; idx += 256) {
        int r = idx / 44, c = idx - r * 44;
        if (c < 43) {
            qtile[r * TILE_WQ + c] =
                (unsigned long long)pairs[r * PAIR_W + c]
              | ((unsigned long long)pairs[r * PAIR_W + c + 2] << 32);
        }
    }
    __syncthreads();

    const int py = py0 + wrp;
    const float centerf = inb[py * W + px0 + lane];
    const bool exY = (py < 4) | (py >= H - 4);   // warp-uniform

    const int o0 = offs[lane];
    const int o1 = offs[lane + 32];
    const int o2 = offs[lane + 64];
    const int o3 = (lane < 30) ? offs[lane + 96] : 0;
    const bool has3 = (lane < 30);

    const unsigned long long* qrow = &qtile[(wrp + 4) * TILE_WQ + 7];
    unsigned* hst = &hist[wrp][0];
    float myscale = 0.0f;

    #pragma unroll 1
    for (int i = 0; i < 8; ++i) {
        const unsigned long long* p = qrow + 4 * i;
        // one LDS.64 per reference cell: low u32 = (P,Q) keys, high u32 = (R,S)
        const unsigned long long w0 = p[o0];
        const unsigned long long w1 = p[o1];
        const unsigned long long w2 = p[o2];
        const unsigned long long w3 = p[o3];
        const unsigned a0 = (unsigned)w0, b0 = (unsigned)(w0 >> 32);
        const unsigned a1 = (unsigned)w1, b1 = (unsigned)(w1 >> 32);
        const unsigned a2 = (unsigned)w2, b2 = (unsigned)(w2 >> 32);
        const unsigned a3 = has3 ? (unsigned)w3 : SENT2;
        const unsigned b3 = has3 ? (unsigned)(w3 >> 32) : SENT2;

        // ---- byte-packed 128-bin histogram (bin = key>>8; SENT->bin 123, harmless) ----
        *reinterpret_cast<uint4*>(&hst[lane * 4]) = make_uint4(0u, 0u, 0u, 0u);
        __syncwarp();
        atomicAdd(&hst[(a0 >> 8) & 0xFFu], 1u);         atomicAdd(&hst[a0 >> 24], 0x100u);
        atomicAdd(&hst[(a1 >> 8) & 0xFFu], 1u);         atomicAdd(&hst[a1 >> 24], 0x100u);
        atomicAdd(&hst[(a2 >> 8) & 0xFFu], 1u);         atomicAdd(&hst[a2 >> 24], 0x100u);
        atomicAdd(&hst[(a3 >> 8) & 0xFFu], 1u);         atomicAdd(&hst[a3 >> 24], 0x100u);
        atomicAdd(&hst[(b0 >> 8) & 0xFFu], 0x10000u);   atomicAdd(&hst[b0 >> 24], 0x1000000u);
        atomicAdd(&hst[(b1 >> 8) & 0xFFu], 0x10000u);   atomicAdd(&hst[b1 >> 24], 0x1000000u);
        atomicAdd(&hst[(b2 >> 8) & 0xFFu], 0x10000u);   atomicAdd(&hst[b2 >> 24], 0x1000000u);
        atomicAdd(&hst[(b3 >> 8) & 0xFFu], 0x10000u);   atomicAdd(&hst[b3 >> 24], 0x1000000u);
        __syncwarp();

        // ---- lane-serial byte-SIMD prefix + ONE packed warp scan (bytes <= 128) ----
        const uint4 cw = *reinterpret_cast<const uint4*>(&hst[lane * 4]);
        unsigned q0 = cw.x;
        unsigned q1 = q0 + cw.y;
        unsigned q2 = q1 + cw.z;
        unsigned q3 = q2 + cw.w;
        unsigned incl = q3;
        #pragma unroll
        for (int d = 1; d < 32; d <<= 1) {
            unsigned t = __shfl_up_sync(0xffffffffu, incl, d);
            if (lane >= d) incl += t;
        }
        const unsigned excl = incl - q3;
        q0 += excl; q1 += excl; q2 += excl; q3 += excl;

        // ---- byte-SIMD bucket search for all 4 pixels, TWO REDUX total ----
        const unsigned g30 = (((0x9E9E9E9Eu - q0) >> 7) & 0x01010101u)
                           + (((0x9E9E9E9Eu - q1) >> 7) & 0x01010101u)
                           + (((0x9E9E9E9Eu - q2) >> 7) & 0x01010101u)
                           + (((0x9E9E9E9Eu - q3) >> 7) & 0x01010101u);
        const unsigned g94 = (((0xDEDEDEDEu - q0) >> 7) & 0x01010101u)
                           + (((0xDEDEDEDEu - q1) >> 7) & 0x01010101u)
                           + (((0xDEDEDEDEu - q2) >> 7) & 0x01010101u)
                           + (((0xDEDEDEDEu - q3) >> 7) & 0x01010101u);
        const unsigned w30 = __reduce_add_sync(0xffffffffu, g30);  // bytes (bAP,bAQ,bAR,bAS)
        const unsigned w94 = __reduce_add_sync(0xffffffffu, g94);  // bytes (bBP,bBQ,bBR,bBS)

        // bucket base = bin<<8: bytes to halfword-high positions per pair
        const unsigned A2pq = __byte_perm(w30, 0, 0x1404);   // (0,bAP,0,bAQ)
        const unsigned B2pq = __byte_perm(w94, 0, 0x1404);
        const unsigned A2rs = __byte_perm(w30, 0, 0x3424);   // (0,bAR,0,bAS)
        const unsigned B2rs = __byte_perm(w94, 0, 0x3424);

        float s0, s1, s2, s3;
        const int pxP = px0 + 4 * i;
        if (exY | (pxP < 7) | (pxP + 3 >= W - 7)) {
            // window touches zero padding: 8 exact bisection steps inside bucket
            bisect_pair<7, 0>(a0, a1, a2, a3, A2pq, B2pq, s0, s1);
            bisect_pair<7, 0>(b0, b1, b2, b3, A2rs, B2rs, s2, s3);
        } else {
            // clean: 256-wide bucket direct, midpoint +-128 substitution
            bisect_pair<7, 8>(a0, a1, a2, a3, A2pq, B2pq, s0, s1);
            bisect_pair<7, 8>(b0, b1, b2, b3, A2rs, B2rs, s2, s3);
        }
        if (lane == 4 * i)     myscale = s0;
        if (lane == 4 * i + 1) myscale = s1;
        if (lane == 4 * i + 2) myscale = s2;
        if (lane == 4 * i + 3) myscale = s3;
    }

    out[(size_t)bz * H * W + py * W + px0 + lane] = centerf * myscale;
}

extern "C" void kernel_launch(void* const* d_in, const int* in_sizes, int n_in,
                              void* d_out, int out_size)
{
    const float* in = (const float*)d_in[0];
    float* out = (float*)d_out;
    const int H = 512, W = 512;
    const int B = in_sizes[0] / (H * W);

    dim3 grid(W / 32, H / 8, B);
    dim3 block(256);
    tmcfar_kernel<<<grid, block>>>(in, out, H, W);
}